// round 8
// baseline (speedup 1.0000x reference)
#include <cuda_runtime.h>
#include <stdint.h>

// Problem constants: images [64, 3, 512, 512] fp32, PATCH=8, TOP_K=512
#define BATCH   64
#define CH      3
#define HH      512
#define WW      512
#define PP      4096        // patches per image (64x64)
#define TOPK    512
#define NUNSEL  (PP - TOPK)            // 3584 unselected per image (exact)
#define NPATCH  (BATCH * PP)           // 262144
#define BLKS_PER_IMG 16                // contrast blocks per image (4096/256)

#define COPY_BLOCKS  ((BATCH * TOPK) / 8)     // 4096
#define ZERO_BLOCKS  ((BATCH * NUNSEL) / 8)   // 28672

// Scratch (no allocations allowed in kernel_launch)
__device__ unsigned int g_bits[NPATCH];            // contrast as orderable uint bits
__device__ int          g_sel[BATCH * TOPK];       // selected patch idx per image
__device__ int          g_uns[BATCH * NUNSEL];     // unselected patch idx per image
__device__ int          g_cnt[BATCH];              // arrival counters (self-resetting)

// ---------------------------------------------------------------------------
// Shared-memory state for the in-kernel radix select. alignas(16) is
// REQUIRED: sv is accessed through uint4* (128-bit LDS/STS); without it the
// struct gets 4-byte alignment -> misaligned-address trap.
// ---------------------------------------------------------------------------
struct alignas(16) SelSmem {
    unsigned int sv[PP];            // first member: 16B-aligned
    unsigned int hist[256];
    unsigned int sufs[256 + 1];
    unsigned int thr;
    int rank;
    int wsum[8];
    int wexc[8];
};

// ---------------------------------------------------------------------------
// Device function: per-image exact top-512 via 4-pass 8-bit radix select,
// then compact both selected (512) and unselected (3584) index lists.
// Runs with 256 threads. Tie-break matches jax.lax.top_k (lowest index).
// ---------------------------------------------------------------------------
__device__ __noinline__ void do_select(SelSmem* s, int b, int t) {
    int lane = t & 31;
    int warp = t >> 5;

    // Load this image's 4096 contrast bits (L2-hot) into smem.
    {
        const uint4* src = reinterpret_cast<const uint4*>(&g_bits[b * PP]);
        uint4* dst = reinterpret_cast<uint4*>(s->sv);
        #pragma unroll
        for (int i = 0; i < PP / 4 / 256; i++)
            dst[t + i * 256] = src[t + i * 256];
    }
    if (t == 0) { s->thr = 0u; s->rank = TOPK; s->sufs[256] = 0u; }
    __syncthreads();

    unsigned int prefmask = 0u;
    #pragma unroll
    for (int pass = 3; pass >= 0; pass--) {
        int shift = pass * 8;
        s->hist[t] = 0u;
        __syncthreads();
        unsigned int thr = s->thr;
        int rank = s->rank;

        // Warp-aggregated histogram (values are highly concentrated).
        #pragma unroll
        for (int i = 0; i < PP / 256; i++) {
            unsigned int v = s->sv[t + i * 256];
            bool act = ((v & prefmask) == thr);
            unsigned int actmask = __ballot_sync(0xFFFFFFFFu, act);
            if (act) {
                unsigned int bin = (v >> shift) & 255u;
                unsigned int peers = __match_any_sync(actmask, bin);
                if (lane == (__ffs(peers) - 1))
                    atomicAdd(&s->hist[bin], __popc(peers));
            }
        }
        __syncthreads();

        // Parallel suffix sum over 256 bins: sufs[t] = hist[t..255].
        s->sufs[t] = s->hist[t];
        __syncthreads();
        #pragma unroll
        for (int off = 1; off < 256; off <<= 1) {
            unsigned int add = (t + off < 256) ? s->sufs[t + off] : 0u;
            __syncthreads();
            s->sufs[t] += add;
            __syncthreads();
        }

        // Exactly one thread's bin straddles the rank boundary.
        unsigned int above = s->sufs[t + 1];
        if (s->sufs[t] >= (unsigned)rank && above < (unsigned)rank) {
            s->thr  = thr | ((unsigned int)t << shift);
            s->rank = rank - (int)above;            // >= 1
        }
        prefmask |= (0xFFu << shift);
        __syncthreads();
    }

    unsigned int thr = s->thr;      // exact 512th-largest value bits
    int need = s->rank;             // how many of the == thr values to include

    // Each thread owns a contiguous chunk of 16 patches.
    int base = t * 16;

    // ---- stable tie resolution: scan of equal-to-threshold counts ----
    int local_eq = 0;
    #pragma unroll
    for (int k = 0; k < 16; k++)
        local_eq += (s->sv[base + k] == thr) ? 1 : 0;

    int incl = local_eq;
    #pragma unroll
    for (int off = 1; off < 32; off <<= 1) {
        int n = __shfl_up_sync(0xFFFFFFFFu, incl, off);
        if (lane >= off) incl += n;
    }
    if (lane == 31) s->wsum[warp] = incl;
    __syncthreads();
    if (t == 0) {
        int acc = 0;
        #pragma unroll
        for (int w = 0; w < 8; w++) { s->wexc[w] = acc; acc += s->wsum[w]; }
    }
    __syncthreads();
    int run = s->wexc[warp] + (incl - local_eq);   // equals with smaller index

    // ---- build selection bits for my 16 patches ----
    unsigned int selbits = 0u;
    #pragma unroll
    for (int k = 0; k < 16; k++) {
        unsigned int v = s->sv[base + k];
        bool m = false;
        if (v > thr) m = true;
        else if (v == thr) { m = (run < need); run++; }
        selbits |= (m ? 1u : 0u) << k;
    }
    __syncthreads();

    // ---- compact selected + unselected indices via block scan ----
    int local_sel = __popc(selbits);
    int incl2 = local_sel;
    #pragma unroll
    for (int off = 1; off < 32; off <<= 1) {
        int n = __shfl_up_sync(0xFFFFFFFFu, incl2, off);
        if (lane >= off) incl2 += n;
    }
    if (lane == 31) s->wsum[warp] = incl2;
    __syncthreads();
    if (t == 0) {
        int acc = 0;
        #pragma unroll
        for (int w = 0; w < 8; w++) { s->wexc[w] = acc; acc += s->wsum[w]; }
    }
    __syncthreads();
    int pos  = s->wexc[warp] + (incl2 - local_sel);      // selected offset
    int upos = base - pos;                               // unselected offset

    int* sl = &g_sel[b * TOPK];
    int* ul = &g_uns[b * NUNSEL];
    #pragma unroll
    for (int k = 0; k < 16; k++) {
        int pidx = base + k;
        if ((selbits >> k) & 1u) sl[pos++] = pidx;
        else                     ul[upos++] = pidx;
    }
}

// ---------------------------------------------------------------------------
// Kernel 1: per-patch min/max -> contrast bits; the LAST block to finish per
// image runs the radix select for that image (overlaps with other images'
// contrast work -> select latency hidden).
// ---------------------------------------------------------------------------
__global__ void __launch_bounds__(256, 8) contrast_select_kernel(const float* __restrict__ in) {
    __shared__ SelSmem s;
    __shared__ int s_old;

    int t    = threadIdx.x;
    int idx  = blockIdx.x * 256 + t;                // patch id in [0, NPATCH)
    int b    = idx >> 12;
    int pidx = idx & 4095;
    int ph   = pidx >> 6;
    int pw   = pidx & 63;

    const float4* in4 = reinterpret_cast<const float4*>(in);
    float mx = -1e30f, mn = 1e30f;

    #pragma unroll
    for (int c = 0; c < CH; c++) {
        #pragma unroll
        for (int py = 0; py < 8; py++) {
            int base = ((b * CH + c) * HH + ph * 8 + py) * (WW / 4) + pw * 2;
            float4 v0 = in4[base];
            float4 v1 = in4[base + 1];
            mx = fmaxf(mx, fmaxf(fmaxf(v0.x, v0.y), fmaxf(v0.z, v0.w)));
            mx = fmaxf(mx, fmaxf(fmaxf(v1.x, v1.y), fmaxf(v1.z, v1.w)));
            mn = fminf(mn, fminf(fminf(v0.x, v0.y), fminf(v0.z, v0.w)));
            mn = fminf(mn, fminf(fminf(v1.x, v1.y), fminf(v1.z, v1.w)));
        }
    }

    // Match JAX fp32 IEEE exactly: ((mx - mn) + eps) / (mx + mn), no contraction.
    float num = __fadd_rn(__fsub_rn(mx, mn), 1e-8f);
    float den = __fadd_rn(mx, mn);
    float ctr = __fdiv_rn(num, den);
    // ctr > 0 always -> positive-float bits order identically to float order.
    g_bits[idx] = __float_as_uint(ctr);

    // Publish writes, then count this block's arrival for its image.
    __threadfence();
    __syncthreads();
    if (t == 0) s_old = atomicAdd(&g_cnt[b], 1);
    __syncthreads();

    if (s_old == BLKS_PER_IMG - 1) {
        // All 16 blocks of image b done; their g_bits writes are published.
        __threadfence();                 // acquire side
        if (t == 0) g_cnt[b] = 0;        // self-reset for next graph replay
        do_select(&s, b, t);
    }
}

// ---------------------------------------------------------------------------
// Kernel 2: single output pass, roles interleaved 1:7 (copy:zero) so the
// gather-read latency of copy blocks hides under the zero-store stream.
// 8 patches per 384-thread block, 48 float4 per patch, uniform per block.
// Every output byte written exactly once, streaming-hinted.
// ---------------------------------------------------------------------------
__global__ void __launch_bounds__(384) output_kernel(const float* __restrict__ in,
                                                     float* __restrict__ out) {
    int t   = threadIdx.x;
    int lp  = t / 48;                        // 0..7 local patch
    int f4  = t - lp * 48;                   // 0..47 float4 slot within patch
    float4* out4 = reinterpret_cast<float4*>(out);

    int grp = blockIdx.x >> 3;               // 0..4095
    int sub = blockIdx.x & 7;                // 0 -> copy, 1..7 -> zero

    if (sub == 0) {
        int j    = grp * 8 + lp;             // dense selected index [0, 32768)
        int b    = j >> 9;                   // 512 selected per image
        int pidx = g_sel[j];
        int gp   = b * PP + pidx;
        int ph   = pidx >> 6;
        int pw   = pidx & 63;

        int c   = f4 >> 4;                   // 0..2
        int rem = f4 & 15;
        int py  = rem >> 1;                  // 0..7
        int q   = rem & 1;                   // half-row (4 floats)

        const float4* in4 = reinterpret_cast<const float4*>(in);
        float4 v = __ldcs(&in4[((b * CH + c) * HH + ph * 8 + py) * (WW / 4) + pw * 2 + q]);
        __stcs(&out4[(size_t)gp * 48 + f4], v);
    } else {
        int zb   = grp * 7 + (sub - 1);      // dense zero-block id [0, 28672)
        int j    = zb * 8 + lp;              // dense unselected idx
        int b    = j / NUNSEL;
        int u    = j - b * NUNSEL;
        int pidx = g_uns[b * NUNSEL + u];
        int gp   = b * PP + pidx;
        const float4 z = make_float4(0.f, 0.f, 0.f, 0.f);
        __stcs(&out4[(size_t)gp * 48 + f4], z);
    }
}

// ---------------------------------------------------------------------------
extern "C" void kernel_launch(void* const* d_in, const int* in_sizes, int n_in,
                              void* d_out, int out_size) {
    const float* in  = (const float*)d_in[0];
    float*       out = (float*)d_out;

    contrast_select_kernel<<<NPATCH / 256, 256>>>(in);
    output_kernel<<<COPY_BLOCKS + ZERO_BLOCKS, 384>>>(in, out);
}

// round 9
// speedup vs baseline: 1.1204x; 1.1204x over previous
#include <cuda_runtime.h>
#include <stdint.h>

// Problem constants: images [64, 3, 512, 512] fp32, PATCH=8, TOP_K=512
#define BATCH   64
#define CH      3
#define HH      512
#define WW      512
#define PP      4096        // patches per image (64x64)
#define TOPK    512
#define NUNSEL  (PP - TOPK)            // 3584 unselected per image (exact)
#define NPATCH  (BATCH * PP)           // 262144

#define OUT_BLOCKS   4096              // output kernel blocks (8 iterations each)
#define ZERO_ITERS   7                 // 7 zero units per block after 1 copy unit

// Scratch (no allocations allowed in kernel_launch)
__device__ unsigned int g_bits[NPATCH];            // contrast as orderable uint bits
__device__ int          g_sel[BATCH * TOPK];       // selected patch idx per image
__device__ int          g_uns[BATCH * NUNSEL];     // unselected patch idx per image

// ---------------------------------------------------------------------------
// Kernel 1: per-patch min/max -> contrast bits. One thread per patch.
// Pure streaming read; ~77-79% DRAM (measured).
// ---------------------------------------------------------------------------
__global__ void __launch_bounds__(256) contrast_kernel(const float* __restrict__ in) {
    int idx  = blockIdx.x * 256 + threadIdx.x;      // patch id in [0, NPATCH)
    int b    = idx >> 12;
    int pidx = idx & 4095;
    int ph   = pidx >> 6;
    int pw   = pidx & 63;

    const float4* in4 = reinterpret_cast<const float4*>(in);
    float mx = -1e30f, mn = 1e30f;

    #pragma unroll
    for (int c = 0; c < CH; c++) {
        #pragma unroll
        for (int py = 0; py < 8; py++) {
            int base = ((b * CH + c) * HH + ph * 8 + py) * (WW / 4) + pw * 2;
            float4 v0 = in4[base];
            float4 v1 = in4[base + 1];
            mx = fmaxf(mx, fmaxf(fmaxf(v0.x, v0.y), fmaxf(v0.z, v0.w)));
            mx = fmaxf(mx, fmaxf(fmaxf(v1.x, v1.y), fmaxf(v1.z, v1.w)));
            mn = fminf(mn, fminf(fminf(v0.x, v0.y), fminf(v0.z, v0.w)));
            mn = fminf(mn, fminf(fminf(v1.x, v1.y), fminf(v1.z, v1.w)));
        }
    }

    // Match JAX fp32 IEEE exactly: ((mx - mn) + eps) / (mx + mn), no contraction.
    float num = __fadd_rn(__fsub_rn(mx, mn), 1e-8f);
    float den = __fadd_rn(mx, mn);
    float ctr = __fdiv_rn(num, den);
    // ctr > 0 always -> positive-float bits order identically to float order.
    g_bits[idx] = __float_as_uint(ctr);
}

// ---------------------------------------------------------------------------
// Kernel 2: per-image exact top-512 via 4-pass 8-bit radix select, then
// compact BOTH selected (512) and unselected (3584) patch index lists.
// Suffix-sum over 256 bins done by ONE warp via shfl (4 syncs/pass, not 19).
// Tie-break matches jax.lax.top_k (lowest index first).
// ---------------------------------------------------------------------------
__global__ void __launch_bounds__(256) select_kernel() {
    __shared__ unsigned int sv[PP];
    __shared__ unsigned int hist[256];
    __shared__ unsigned int sufs[256 + 1];
    __shared__ unsigned int s_thr;
    __shared__ int s_rank;
    __shared__ int wsum[8];
    __shared__ int wexc[8];

    int b = blockIdx.x;
    int t = threadIdx.x;
    int lane = t & 31;
    int warp = t >> 5;

    // Vectorized coalesced load of this image's 4096 contrast bits into smem.
    {
        const uint4* src = reinterpret_cast<const uint4*>(&g_bits[b * PP]);
        uint4* dst = reinterpret_cast<uint4*>(sv);
        #pragma unroll
        for (int i = 0; i < PP / 4 / 256; i++)
            dst[t + i * 256] = src[t + i * 256];
    }
    if (t == 0) { s_thr = 0u; s_rank = TOPK; sufs[256] = 0u; }
    __syncthreads();

    unsigned int prefmask = 0u;
    #pragma unroll
    for (int pass = 3; pass >= 0; pass--) {
        int shift = pass * 8;
        hist[t] = 0u;
        __syncthreads();
        unsigned int thr = s_thr;
        int rank = s_rank;

        // Warp-aggregated histogram (values are highly concentrated).
        #pragma unroll
        for (int i = 0; i < PP / 256; i++) {
            unsigned int v = sv[t + i * 256];
            bool act = ((v & prefmask) == thr);
            unsigned int actmask = __ballot_sync(0xFFFFFFFFu, act);
            if (act) {
                unsigned int bin = (v >> shift) & 255u;
                unsigned int peers = __match_any_sync(actmask, bin);
                if (lane == (__ffs(peers) - 1))
                    atomicAdd(&hist[bin], __popc(peers));
            }
        }
        __syncthreads();

        // Single-warp suffix sum: sufs[i] = hist[i] + ... + hist[255].
        if (warp == 0) {
            int base8 = lane * 8;
            unsigned int chunk = 0;
            #pragma unroll
            for (int k = 0; k < 8; k++) chunk += hist[base8 + k];
            // inclusive suffix scan of chunk across lanes (descending)
            unsigned int suf = chunk;
            #pragma unroll
            for (int off = 1; off < 32; off <<= 1) {
                unsigned int n = __shfl_down_sync(0xFFFFFFFFu, suf, off);
                if (lane + off < 32) suf += n;
            }
            unsigned int run = suf - chunk;      // bins strictly above my chunk
            #pragma unroll
            for (int k = 7; k >= 0; k--) {
                run += hist[base8 + k];
                sufs[base8 + k] = run;
            }
        }
        __syncthreads();

        // Exactly one thread's bin straddles the rank boundary.
        unsigned int above = sufs[t + 1];
        if (sufs[t] >= (unsigned)rank && above < (unsigned)rank) {
            s_thr  = thr | ((unsigned int)t << shift);
            s_rank = rank - (int)above;             // >= 1
        }
        prefmask |= (0xFFu << shift);
        __syncthreads();
    }

    unsigned int thr = s_thr;       // exact 512th-largest value bits
    int need = s_rank;              // how many of the == thr values to include

    // Each thread owns a contiguous chunk of 16 patches.
    int base = t * 16;

    // ---- stable tie resolution: scan of equal-to-threshold counts ----
    int local_eq = 0;
    #pragma unroll
    for (int k = 0; k < 16; k++)
        local_eq += (sv[base + k] == thr) ? 1 : 0;

    int incl = local_eq;
    #pragma unroll
    for (int off = 1; off < 32; off <<= 1) {
        int n = __shfl_up_sync(0xFFFFFFFFu, incl, off);
        if (lane >= off) incl += n;
    }
    if (lane == 31) wsum[warp] = incl;
    __syncthreads();
    if (t == 0) {
        int acc = 0;
        #pragma unroll
        for (int w = 0; w < 8; w++) { wexc[w] = acc; acc += wsum[w]; }
    }
    __syncthreads();
    int run = wexc[warp] + (incl - local_eq);   // equals with smaller index

    // ---- build selection bits for my 16 patches ----
    unsigned int selbits = 0u;
    #pragma unroll
    for (int k = 0; k < 16; k++) {
        unsigned int v = sv[base + k];
        bool m = false;
        if (v > thr) m = true;
        else if (v == thr) { m = (run < need); run++; }
        selbits |= (m ? 1u : 0u) << k;
    }
    __syncthreads();

    // ---- compact selected + unselected indices via block scan ----
    int local_sel = __popc(selbits);
    int incl2 = local_sel;
    #pragma unroll
    for (int off = 1; off < 32; off <<= 1) {
        int n = __shfl_up_sync(0xFFFFFFFFu, incl2, off);
        if (lane >= off) incl2 += n;
    }
    if (lane == 31) wsum[warp] = incl2;
    __syncthreads();
    if (t == 0) {
        int acc = 0;
        #pragma unroll
        for (int w = 0; w < 8; w++) { wexc[w] = acc; acc += wsum[w]; }
    }
    __syncthreads();
    int pos  = wexc[warp] + (incl2 - local_sel);         // selected offset
    int upos = base - pos;                               // unselected offset

    int* sl = &g_sel[b * TOPK];
    int* ul = &g_uns[b * NUNSEL];
    #pragma unroll
    for (int k = 0; k < 16; k++) {
        int pidx = base + k;
        if ((selbits >> k) & 1u) sl[pos++] = pidx;
        else                     ul[upos++] = pidx;
    }
}

// ---------------------------------------------------------------------------
// Kernel 3: single output pass, 4096 blocks x 8 units each (1 copy + 7 zero).
// Per thread: issue gather LDG first, then 7 independent zero stores (hide
// the gather latency), then the copy store last. 8 patches per unit,
// 48 float4 per patch. Every output byte written exactly once.
// ---------------------------------------------------------------------------
__global__ void __launch_bounds__(384) output_kernel(const float* __restrict__ in,
                                                     float* __restrict__ out) {
    int t   = threadIdx.x;
    int lp  = t / 48;                        // 0..7 local patch within unit
    int f4  = t - lp * 48;                   // 0..47 float4 slot within patch
    float4* out4 = reinterpret_cast<float4*>(out);

    // ---- copy unit (issue the gather load NOW, store at the end) ----
    int cj    = blockIdx.x * 8 + lp;         // dense selected index [0, 32768)
    int cb    = cj >> 9;                     // 512 selected per image
    int cpidx = g_sel[cj];
    long cgp  = (long)cb * PP + cpidx;
    {
        // fall through to gather issue below
    }
    int ph  = cpidx >> 6;
    int pw  = cpidx & 63;
    int c   = f4 >> 4;                       // 0..2
    int rem = f4 & 15;
    int py  = rem >> 1;                      // 0..7
    int q   = rem & 1;                       // half-row (4 floats)
    const float4* in4 = reinterpret_cast<const float4*>(in);
    float4 v = __ldcs(&in4[((cb * CH + c) * HH + ph * 8 + py) * (WW / 4) + pw * 2 + q]);

    // ---- 7 zero units: pure stores, independent of the gather above ----
    const float4 z = make_float4(0.f, 0.f, 0.f, 0.f);
    #pragma unroll
    for (int i = 0; i < ZERO_ITERS; i++) {
        int j    = (blockIdx.x + i * OUT_BLOCKS) * 8 + lp;   // unselected idx
        int b    = j / NUNSEL;
        int u    = j - b * NUNSEL;
        int pidx = g_uns[b * NUNSEL + u];
        __stcs(&out4[((size_t)b * PP + pidx) * 48 + f4], z);
    }

    // ---- copy store (gather latency hidden under the zero stream) ----
    __stcs(&out4[(size_t)cgp * 48 + f4], v);
}

// ---------------------------------------------------------------------------
extern "C" void kernel_launch(void* const* d_in, const int* in_sizes, int n_in,
                              void* d_out, int out_size) {
    const float* in  = (const float*)d_in[0];
    float*       out = (float*)d_out;

    contrast_kernel<<<NPATCH / 256, 256>>>(in);
    select_kernel<<<BATCH, 256>>>();
    output_kernel<<<OUT_BLOCKS, 384>>>(in, out);
}

// round 10
// speedup vs baseline: 1.1705x; 1.0447x over previous
#include <cuda_runtime.h>
#include <stdint.h>

// Problem constants: images [64, 3, 512, 512] fp32, PATCH=8, TOP_K=512
#define BATCH   64
#define CH      3
#define HH      512
#define WW      512
#define PP      4096        // patches per image (64x64)
#define TOPK    512
#define NPATCH  (BATCH * PP)           // 262144
#define OUT_F4  (NPATCH * 48)          // total float4 in output (12.58M)

// Scratch (no allocations allowed in kernel_launch)
__device__ unsigned int g_bits[NPATCH];            // contrast as orderable uint bits
__device__ int          g_sel[BATCH * TOPK];       // selected patch idx per image

// ---------------------------------------------------------------------------
// Kernel 1: per-patch min/max -> contrast bits. One thread per patch.
// Pure streaming read; ~77% DRAM (measured).
// ---------------------------------------------------------------------------
__global__ void __launch_bounds__(256) contrast_kernel(const float* __restrict__ in) {
    int idx  = blockIdx.x * 256 + threadIdx.x;      // patch id in [0, NPATCH)
    int b    = idx >> 12;
    int pidx = idx & 4095;
    int ph   = pidx >> 6;
    int pw   = pidx & 63;

    const float4* in4 = reinterpret_cast<const float4*>(in);
    float mx = -1e30f, mn = 1e30f;

    #pragma unroll
    for (int c = 0; c < CH; c++) {
        #pragma unroll
        for (int py = 0; py < 8; py++) {
            int base = ((b * CH + c) * HH + ph * 8 + py) * (WW / 4) + pw * 2;
            float4 v0 = in4[base];
            float4 v1 = in4[base + 1];
            mx = fmaxf(mx, fmaxf(fmaxf(v0.x, v0.y), fmaxf(v0.z, v0.w)));
            mx = fmaxf(mx, fmaxf(fmaxf(v1.x, v1.y), fmaxf(v1.z, v1.w)));
            mn = fminf(mn, fminf(fminf(v0.x, v0.y), fminf(v0.z, v0.w)));
            mn = fminf(mn, fminf(fminf(v1.x, v1.y), fminf(v1.z, v1.w)));
        }
    }

    // Match JAX fp32 IEEE exactly: ((mx - mn) + eps) / (mx + mn), no contraction.
    float num = __fadd_rn(__fsub_rn(mx, mn), 1e-8f);
    float den = __fadd_rn(mx, mn);
    float ctr = __fdiv_rn(num, den);
    // ctr > 0 always -> positive-float bits order identically to float order.
    g_bits[idx] = __float_as_uint(ctr);
}

// ---------------------------------------------------------------------------
// Kernel 2: per-image exact top-512 via 4-pass 8-bit radix select, 1024
// threads per block (histogram loop = 4 iterations/pass). Compacts the
// selected (512) index list. Tie-break matches jax.lax.top_k (lowest index).
// ---------------------------------------------------------------------------
__global__ void __launch_bounds__(1024) select_kernel() {
    __shared__ unsigned int sv[PP];
    __shared__ unsigned int hist[256];
    __shared__ unsigned int sufs[256 + 1];
    __shared__ unsigned int s_thr;
    __shared__ int s_rank;
    __shared__ int wsum[32];
    __shared__ int wexc[32];

    int b = blockIdx.x;
    int t = threadIdx.x;
    int lane = t & 31;
    int warp = t >> 5;

    // Coalesced load: 1024 threads x 1 uint4 = 4096 uints.
    {
        const uint4* src = reinterpret_cast<const uint4*>(&g_bits[b * PP]);
        reinterpret_cast<uint4*>(sv)[t] = src[t];
    }
    if (t == 0) { s_thr = 0u; s_rank = TOPK; sufs[256] = 0u; }
    __syncthreads();

    unsigned int prefmask = 0u;
    #pragma unroll
    for (int pass = 3; pass >= 0; pass--) {
        int shift = pass * 8;
        if (t < 256) hist[t] = 0u;
        __syncthreads();
        unsigned int thr = s_thr;
        int rank = s_rank;

        // Warp-aggregated histogram (values are highly concentrated).
        #pragma unroll
        for (int i = 0; i < PP / 1024; i++) {
            unsigned int v = sv[t + i * 1024];
            bool act = ((v & prefmask) == thr);
            unsigned int actmask = __ballot_sync(0xFFFFFFFFu, act);
            if (act) {
                unsigned int bin = (v >> shift) & 255u;
                unsigned int peers = __match_any_sync(actmask, bin);
                if (lane == (__ffs(peers) - 1))
                    atomicAdd(&hist[bin], __popc(peers));
            }
        }
        __syncthreads();

        // Single-warp suffix sum: sufs[i] = hist[i] + ... + hist[255].
        if (warp == 0) {
            int base8 = lane * 8;
            unsigned int chunk = 0;
            #pragma unroll
            for (int k = 0; k < 8; k++) chunk += hist[base8 + k];
            unsigned int suf = chunk;
            #pragma unroll
            for (int off = 1; off < 32; off <<= 1) {
                unsigned int n = __shfl_down_sync(0xFFFFFFFFu, suf, off);
                if (lane + off < 32) suf += n;
            }
            unsigned int run = suf - chunk;      // bins strictly above my chunk
            #pragma unroll
            for (int k = 7; k >= 0; k--) {
                run += hist[base8 + k];
                sufs[base8 + k] = run;
            }
        }
        __syncthreads();

        // Exactly one thread's bin straddles the rank boundary.
        if (t < 256) {
            unsigned int above = sufs[t + 1];
            if (sufs[t] >= (unsigned)rank && above < (unsigned)rank) {
                s_thr  = thr | ((unsigned int)t << shift);
                s_rank = rank - (int)above;         // >= 1
            }
        }
        prefmask |= (0xFFu << shift);
        __syncthreads();
    }

    unsigned int thr = s_thr;       // exact 512th-largest value bits
    int need = s_rank;              // how many of the == thr values to include

    // Each thread owns a contiguous chunk of 4 patches.
    int base = t * 4;
    unsigned int v0 = sv[base + 0], v1 = sv[base + 1];
    unsigned int v2 = sv[base + 2], v3 = sv[base + 3];

    // ---- stable tie resolution: block scan of equal-to-threshold counts ----
    int local_eq = (v0 == thr) + (v1 == thr) + (v2 == thr) + (v3 == thr);
    int incl = local_eq;
    #pragma unroll
    for (int off = 1; off < 32; off <<= 1) {
        int n = __shfl_up_sync(0xFFFFFFFFu, incl, off);
        if (lane >= off) incl += n;
    }
    if (lane == 31) wsum[warp] = incl;
    __syncthreads();
    if (warp == 0) {
        int x = wsum[lane];
        int ix = x;
        #pragma unroll
        for (int off = 1; off < 32; off <<= 1) {
            int n = __shfl_up_sync(0xFFFFFFFFu, ix, off);
            if (lane >= off) ix += n;
        }
        wexc[lane] = ix - x;
    }
    __syncthreads();
    int run = wexc[warp] + (incl - local_eq);   // equals with smaller index

    // ---- build selection bits for my 4 patches ----
    unsigned int selbits = 0u;
    {
        unsigned int vv[4] = {v0, v1, v2, v3};
        #pragma unroll
        for (int k = 0; k < 4; k++) {
            bool m = false;
            if (vv[k] > thr) m = true;
            else if (vv[k] == thr) { m = (run < need); run++; }
            selbits |= (m ? 1u : 0u) << k;
        }
    }
    __syncthreads();

    // ---- compact selected indices via block scan ----
    int local_sel = __popc(selbits);
    int incl2 = local_sel;
    #pragma unroll
    for (int off = 1; off < 32; off <<= 1) {
        int n = __shfl_up_sync(0xFFFFFFFFu, incl2, off);
        if (lane >= off) incl2 += n;
    }
    if (lane == 31) wsum[warp] = incl2;
    __syncthreads();
    if (warp == 0) {
        int x = wsum[lane];
        int ix = x;
        #pragma unroll
        for (int off = 1; off < 32; off <<= 1) {
            int n = __shfl_up_sync(0xFFFFFFFFu, ix, off);
            if (lane >= off) ix += n;
        }
        wexc[lane] = ix - x;
    }
    __syncthreads();
    int pos = wexc[warp] + (incl2 - local_sel);

    int* sl = &g_sel[b * TOPK];
    #pragma unroll
    for (int k = 0; k < 4; k++) {
        if ((selbits >> k) & 1u)
            sl[pos++] = base + k;
    }
}

// ---------------------------------------------------------------------------
// Kernel 3: zero the ENTIRE output. Pure linear float4 stores, no index
// loads, no divergence — mirror of the contrast read stream.
// 4096 blocks x 256 threads x 12 stores, contiguous 48KB chunk per block.
// ---------------------------------------------------------------------------
__global__ void __launch_bounds__(256) zero_kernel(float* __restrict__ out) {
    float4* out4 = reinterpret_cast<float4*>(out);
    size_t base = (size_t)blockIdx.x * (256 * 12) + threadIdx.x;
    const float4 z = make_float4(0.f, 0.f, 0.f, 0.f);
    #pragma unroll
    for (int i = 0; i < 12; i++)
        __stcs(&out4[base + (size_t)i * 256], z);
}

// ---------------------------------------------------------------------------
// Kernel 4: copy ONLY the selected patches (dense list — exactly 512/image).
// 8 patches per 384-thread block; pure gather+store, isolated from the zero
// stream so neither degrades the other.
// ---------------------------------------------------------------------------
__global__ void __launch_bounds__(384) copy_kernel(const float* __restrict__ in,
                                                   float* __restrict__ out) {
    int t    = threadIdx.x;
    int lp   = t / 48;                       // 0..7 local patch
    int f4   = t - lp * 48;                  // 0..47 float4 slot within patch
    int j    = blockIdx.x * 8 + lp;          // dense selected index [0, 32768)
    int b    = j >> 9;                       // 512 selected per image
    int pidx = g_sel[j];
    int ph   = pidx >> 6;
    int pw   = pidx & 63;

    int c   = f4 >> 4;                       // 0..2
    int rem = f4 & 15;
    int py  = rem >> 1;                      // 0..7
    int q   = rem & 1;                       // half-row (4 floats)

    const float4* in4 = reinterpret_cast<const float4*>(in);
    float4 v = __ldcs(&in4[((b * CH + c) * HH + ph * 8 + py) * (WW / 4) + pw * 2 + q]);
    __stcs(&reinterpret_cast<float4*>(out)[((size_t)b * PP + pidx) * 48 + f4], v);
}

// ---------------------------------------------------------------------------
extern "C" void kernel_launch(void* const* d_in, const int* in_sizes, int n_in,
                              void* d_out, int out_size) {
    const float* in  = (const float*)d_in[0];
    float*       out = (float*)d_out;

    contrast_kernel<<<NPATCH / 256, 256>>>(in);
    select_kernel<<<BATCH, 1024>>>();
    zero_kernel<<<OUT_F4 / (256 * 12), 256>>>(out);
    copy_kernel<<<(BATCH * TOPK) / 8, 384>>>(in, out);
}